// round 10
// baseline (speedup 1.0000x reference)
#include <cuda_runtime.h>
#include <stdint.h>

#define NDOF_MAX 1000000

__device__ float g_u1[NDOF_MAX];

// Kernel A: u1[bc[i]] = w[i] * u[bc[i]] (bc is arange -> coalesced), F[i] = 0.
// 8 DOFs per thread (two int4/float4 pairs).
__global__ void prep_kernel(const float* __restrict__ u,
                            const float4* __restrict__ w4,
                            const int4* __restrict__ bc4,
                            float4* __restrict__ F4,
                            int n4)   // number of float4 groups (NDOF/4)
{
    int i = (blockIdx.x * blockDim.x + threadIdx.x) * 2;
    #pragma unroll
    for (int t = 0; t < 2; t++, i++) {
        if (i < n4) {
            int4 b = bc4[i];
            float4 w = w4[i];
            g_u1[b.x] = w.x * __ldg(&u[b.x]);
            g_u1[b.y] = w.y * __ldg(&u[b.y]);
            g_u1[b.z] = w.z * __ldg(&u[b.z]);
            g_u1[b.w] = w.w * __ldg(&u[b.w]);
            F4[i] = make_float4(0.f, 0.f, 0.f, 0.f);
        }
    }
}

// Kernel B (best measured config, R9): flat grid, 1 elem/thread,
// edof -> __ldcg gathers (L2-direct, no L1 allocation) -> ke -> FMA + RED.
__global__ void __launch_bounds__(256, 6) assemble_kernel(
    const int* __restrict__ edof,           // [E,8] int32
    const float* __restrict__ ke,           // [E,8,8]
    float* __restrict__ F,                  // [NDOF]
    int E)
{
    int e = blockIdx.x * blockDim.x + threadIdx.x;
    if (e >= E) return;

    // 1) element DOF indices (32 B coalesced) — longest dep chain first
    const int4* erow = reinterpret_cast<const int4*>(edof + (size_t)e * 8);
    int4 i0 = erow[0];
    int4 i1 = erow[1];
    int idx[8] = { i0.x, i0.y, i0.z, i0.w, i1.x, i1.y, i1.z, i1.w };

    // 2) gathers: L2-direct, bypass L1 allocation
    float ue[8];
    #pragma unroll
    for (int j = 0; j < 8; j++) ue[j] = __ldcg(&g_u1[idx[j]]);

    // 3) ke rows: 16 independent float4 loads (hide gather latency under them)
    const float4* kv = reinterpret_cast<const float4*>(ke + (size_t)e * 64);
    float4 k[16];
    #pragma unroll
    for (int i = 0; i < 16; i++) k[i] = kv[i];

    // 4) matvec + fire-and-forget scatter-add
    #pragma unroll
    for (int i = 0; i < 8; i++) {
        float4 a = k[i * 2 + 0];
        float4 b = k[i * 2 + 1];
        float s = a.x*ue[0] + a.y*ue[1] + a.z*ue[2] + a.w*ue[3]
                + b.x*ue[4] + b.y*ue[5] + b.z*ue[6] + b.w*ue[7];
        atomicAdd(&F[idx[i]], s);
    }
}

extern "C" void kernel_launch(void* const* d_in, const int* in_sizes, int n_in,
                              void* d_out, int out_size)
{
    const float* u    = (const float*)d_in[0];
    const float* w    = (const float*)d_in[1];
    const int*   bc   = (const int*)d_in[2];
    const int*   edof = (const int*)d_in[3];
    const float* ke   = (const float*)d_in[4];
    float* F = (float*)d_out;

    int ndof = in_sizes[0];            // 2*NNODE (divisible by 4)
    int E    = in_sizes[3] / 8;        // NELEM

    int n4 = ndof / 4;
    int nthreads = (n4 + 1) / 2;
    prep_kernel<<<(nthreads + 255) / 256, 256>>>(
        u, (const float4*)w, (const int4*)bc, (float4*)F, n4);

    assemble_kernel<<<(E + 255) / 256, 256>>>(edof, ke, F, E);
}

// round 11
// speedup vs baseline: 1.0347x; 1.0347x over previous
#include <cuda_runtime.h>
#include <stdint.h>

#define NDOF_MAX 1000000

__device__ float g_u1[NDOF_MAX];

// Kernel A (R8 config — best measured gap): u1[bc[i]] = w[i] * u[bc[i]]
// (bc is arange -> coalesced) and F[i] = 0. One int4/float4 group per thread.
__global__ void prep_kernel(const float* __restrict__ u,
                            const float4* __restrict__ w4,
                            const int4* __restrict__ bc4,
                            float4* __restrict__ F4,
                            int n4)
{
    int i = blockIdx.x * blockDim.x + threadIdx.x;
    if (i < n4) {
        int4 b = bc4[i];
        float4 w = w4[i];
        g_u1[b.x] = w.x * __ldg(&u[b.x]);
        g_u1[b.y] = w.y * __ldg(&u[b.y]);
        g_u1[b.z] = w.z * __ldg(&u[b.z]);
        g_u1[b.w] = w.w * __ldg(&u[b.w]);
        F4[i] = make_float4(0.f, 0.f, 0.f, 0.f);
    }
}

// Kernel B (R9 config — best measured assemble, 59.3us): flat grid,
// 1 elem/thread, edof -> __ldcg gathers (L2-direct) -> ke -> FMA + RED.
__global__ void __launch_bounds__(256, 6) assemble_kernel(
    const int* __restrict__ edof,           // [E,8] int32
    const float* __restrict__ ke,           // [E,8,8]
    float* __restrict__ F,                  // [NDOF]
    int E)
{
    int e = blockIdx.x * blockDim.x + threadIdx.x;
    if (e >= E) return;

    // 1) element DOF indices (32 B coalesced) — longest dep chain first
    const int4* erow = reinterpret_cast<const int4*>(edof + (size_t)e * 8);
    int4 i0 = erow[0];
    int4 i1 = erow[1];
    int idx[8] = { i0.x, i0.y, i0.z, i0.w, i1.x, i1.y, i1.z, i1.w };

    // 2) gathers: L2-direct, bypass L1 allocation
    float ue[8];
    #pragma unroll
    for (int j = 0; j < 8; j++) ue[j] = __ldcg(&g_u1[idx[j]]);

    // 3) ke rows: 16 independent float4 loads (hide gather latency under them)
    const float4* kv = reinterpret_cast<const float4*>(ke + (size_t)e * 64);
    float4 k[16];
    #pragma unroll
    for (int i = 0; i < 16; i++) k[i] = kv[i];

    // 4) matvec + fire-and-forget scatter-add
    #pragma unroll
    for (int i = 0; i < 8; i++) {
        float4 a = k[i * 2 + 0];
        float4 b = k[i * 2 + 1];
        float s = a.x*ue[0] + a.y*ue[1] + a.z*ue[2] + a.w*ue[3]
                + b.x*ue[4] + b.y*ue[5] + b.z*ue[6] + b.w*ue[7];
        atomicAdd(&F[idx[i]], s);
    }
}

extern "C" void kernel_launch(void* const* d_in, const int* in_sizes, int n_in,
                              void* d_out, int out_size)
{
    const float* u    = (const float*)d_in[0];
    const float* w    = (const float*)d_in[1];
    const int*   bc   = (const int*)d_in[2];
    const int*   edof = (const int*)d_in[3];
    const float* ke   = (const float*)d_in[4];
    float* F = (float*)d_out;

    int ndof = in_sizes[0];            // 2*NNODE (divisible by 4)
    int E    = in_sizes[3] / 8;        // NELEM

    int n4 = ndof / 4;
    prep_kernel<<<(n4 + 255) / 256, 256>>>(
        u, (const float4*)w, (const int4*)bc, (float4*)F, n4);

    assemble_kernel<<<(E + 255) / 256, 256>>>(edof, ke, F, E);
}